// round 1
// baseline (speedup 1.0000x reference)
#include <cuda_runtime.h>

// Points_Sampler: D-FPS over (B=8, N=32768) points, npoint=2048, then gather
// the xyz planes at the sampled indices -> out (B, 3, 2048) fp32.
//
// One CTA per batch, 1024 threads. temp[] (running min squared distance) lives
// in registers (32 floats/thread). Coordinates are streamed from the planar
// points_xyz_t (B,3,N) input each iteration with coalesced float4 loads.
// Argmax reduction: warp shuffle -> smem -> warp0, with lowest-index tie-break
// to match jnp.argmax first-occurrence semantics. Distance arithmetic uses
// explicit round-to-nearest intrinsics (no FMA contraction) so index selection
// matches the fp32 reference.

constexpr int BATCH    = 8;
constexpr int NPTS     = 32768;
constexpr int NPOINT   = 2048;
constexpr int NTHREADS = 1024;
constexpr int NWARPS   = NTHREADS / 32;          // 32
constexpr int PER_TH   = NPTS / NTHREADS;        // 32 points per thread
constexpr int GROUPS   = PER_TH / 4;             // 8 float4 groups per thread

__global__ __launch_bounds__(NTHREADS, 1)
void fps_gather_kernel(const float* __restrict__ xyz_t, float* __restrict__ out)
{
    const int b = blockIdx.x;
    const float* __restrict__ xs = xyz_t + (size_t)b * 3 * NPTS;
    const float* __restrict__ ys = xs + NPTS;
    const float* __restrict__ zs = xs + 2 * NPTS;
    float* __restrict__ ob = out + (size_t)b * 3 * NPOINT;

    const int tid = threadIdx.x;
    const int w   = tid >> 5;
    const int l   = tid & 31;
    // Warp w owns points [w*1024, (w+1)*1024). Lane l takes float4 group
    // (base + i*512B): warp instruction covers 512 contiguous bytes -> 4 full
    // 128B lines per LDG.128 (optimal bytes/wavefront).
    const int base = w * 1024 + l * 4;

    __shared__ float s_val[NWARPS];
    __shared__ int   s_idx[NWARPS];
    __shared__ float s_lx, s_ly, s_lz;

    float temp[PER_TH];
#pragma unroll
    for (int i = 0; i < PER_TH; ++i) temp[i] = 1e10f;

    if (tid == 0) {
        const float lx = xs[0], ly = ys[0], lz = zs[0];
        s_lx = lx; s_ly = ly; s_lz = lz;
        // idx[0] = 0 by definition
        ob[0]          = lx;
        ob[NPOINT]     = ly;
        ob[2 * NPOINT] = lz;
    }
    __syncthreads();

    for (int j = 1; j < NPOINT; ++j) {
        const float lx = s_lx, ly = s_ly, lz = s_lz;

        float bv = -1.0f;   // all temps are >= 0 after first update
        int   bs = 0;       // packed local slot (i*4 + k); ascending scan keeps
                            // the first occurrence on ties within a thread
#pragma unroll
        for (int i = 0; i < GROUPS; ++i) {
            const int p = base + i * (NTHREADS / 8) * 4;  // base + i*512 floats? no:
            // each warp region is 1024 points; group stride within region is
            // 32 lanes * 4 floats = 128 points.
            (void)p;
        }
        // (re-done below with the correct stride)
        bv = -1.0f; bs = 0;
#pragma unroll
        for (int i = 0; i < GROUPS; ++i) {
            const int p = base + i * 128;                 // 128 points per group row
            const float4 x4 = *reinterpret_cast<const float4*>(xs + p);
            const float4 y4 = *reinterpret_cast<const float4*>(ys + p);
            const float4 z4 = *reinterpret_cast<const float4*>(zs + p);
            const float xv[4] = {x4.x, x4.y, x4.z, x4.w};
            const float yv[4] = {y4.x, y4.y, y4.z, y4.w};
            const float zv[4] = {z4.x, z4.y, z4.z, z4.w};
#pragma unroll
            for (int k = 0; k < 4; ++k) {
                const float dx = __fsub_rn(xv[k], lx);
                const float dy = __fsub_rn(yv[k], ly);
                const float dz = __fsub_rn(zv[k], lz);
                const float d2 = __fadd_rn(
                    __fadd_rn(__fmul_rn(dx, dx), __fmul_rn(dy, dy)),
                    __fmul_rn(dz, dz));
                float t = temp[i * 4 + k];
                t = fminf(t, d2);
                temp[i * 4 + k] = t;
                if (t > bv) { bv = t; bs = i * 4 + k; }
            }
        }

        // Recover the global point index for this thread's best slot.
        int bi = base + ((bs >> 2) << 7) + (bs & 3);

        // Warp-level argmax reduce, lowest index wins ties.
#pragma unroll
        for (int off = 16; off; off >>= 1) {
            const float ov = __shfl_down_sync(0xffffffffu, bv, off);
            const int   oi = __shfl_down_sync(0xffffffffu, bi, off);
            if (ov > bv || (ov == bv && oi < bi)) { bv = ov; bi = oi; }
        }
        if (l == 0) { s_val[w] = bv; s_idx[w] = bi; }
        __syncthreads();

        if (w == 0) {
            float v = s_val[l];
            int   ii = s_idx[l];
#pragma unroll
            for (int off = 16; off; off >>= 1) {
                const float ov = __shfl_down_sync(0xffffffffu, v, off);
                const int   oi = __shfl_down_sync(0xffffffffu, ii, off);
                if (ov > v || (ov == v && oi < ii)) { v = ov; ii = oi; }
            }
            if (l == 0) {
                const float nx = __ldg(xs + ii);
                const float ny = __ldg(ys + ii);
                const float nz = __ldg(zs + ii);
                s_lx = nx; s_ly = ny; s_lz = nz;
                ob[j]              = nx;
                ob[NPOINT + j]     = ny;
                ob[2 * NPOINT + j] = nz;
            }
        }
        __syncthreads();
    }
}

extern "C" void kernel_launch(void* const* d_in, const int* in_sizes, int n_in,
                              void* d_out, int out_size)
{
    (void)in_sizes; (void)n_in; (void)out_size;
    const float* xyz_t = (const float*)d_in[1];   // points_xyz_t: (B, 3, N)
    float* out = (float*)d_out;                   // (B, 3, NPOINT)
    fps_gather_kernel<<<BATCH, NTHREADS>>>(xyz_t, out);
}

// round 2
// speedup vs baseline: 2.7094x; 2.7094x over previous
#include <cuda_runtime.h>
#include <cstdint>

// D-FPS (B=8, N=32768, npoint=2048) + gather xyz -> out (B,3,2048) fp32.
//
// One 8-CTA cluster per batch (64 CTAs total, 512 threads each). Each thread
// owns 8 points; coordinates AND the running-min temp array live entirely in
// registers, so the per-iteration inner loop is pure ALU (no memory stream).
// Global argmax per iteration: monotone u64 key = (val_bits<<32) | ~idx
// (vals >= 0, so float bit order == value order; ~idx -> lowest index wins
// ties, matching jnp.argmax first-occurrence). Warp shuffle -> smem -> warp0,
// then the CTA leader pushes its candidate {key,x,y,z} into every cluster
// CTA's smem slot via mapa + st.shared::cluster, followed by ONE
// barrier.cluster (arrive=release orders the remote stores, wait=acquire).
// Slots are double-buffered by iteration parity so no second sync is needed.
// After the sync every thread reduces the 8 candidates locally and picks up
// the winner's coords straight from its own smem.

constexpr int BATCH   = 8;
constexpr int NPTS    = 32768;
constexpr int NPOINT  = 2048;
constexpr int CLUSTER = 8;
constexpr int T       = 512;
constexpr int PER_CTA = NPTS / CLUSTER;  // 4096
constexpr int P       = PER_CTA / T;     // 8 points per thread
constexpr int NW      = T / 32;          // 16 warps

struct __align__(8) Slot {
    unsigned long long key;   // offset 0
    float x, y, z;            // offsets 8, 12, 16
    float pad;                // -> 24 bytes total
};

__device__ __forceinline__ uint32_t smem_u32(const void* p) {
    uint32_t a;
    asm("{ .reg .u64 t; cvta.to.shared.u64 t, %1; cvt.u32.u64 %0, t; }"
        : "=r"(a) : "l"(p));
    return a;
}

__global__ __launch_bounds__(T, 1) __cluster_dims__(CLUSTER, 1, 1)
void fps_cluster_kernel(const float* __restrict__ xyz_t, float* __restrict__ out)
{
    const int b = blockIdx.x / CLUSTER;
    uint32_t rank;
    asm("mov.u32 %0, %%cluster_ctarank;" : "=r"(rank));

    const float* __restrict__ xs = xyz_t + (size_t)b * 3 * NPTS;
    const float* __restrict__ ys = xs + NPTS;
    const float* __restrict__ zs = xs + 2 * NPTS;
    float* __restrict__ ob = out + (size_t)b * 3 * NPOINT;

    const int tid = threadIdx.x;
    const int w = tid >> 5, l = tid & 31;
    const int pbase = (int)rank * PER_CTA;

    __shared__ unsigned long long s_wkey[NW];
    __shared__ Slot s_slot[2][CLUSTER];

    // Register-resident coordinates + running min distance.
    float xr[P], yr[P], zr[P], tmp[P];
#pragma unroll
    for (int i = 0; i < P; ++i) {
        const int g = pbase + i * T + tid;   // warp-coalesced (tid contiguous)
        xr[i] = xs[g];
        yr[i] = ys[g];
        zr[i] = zs[g];
        tmp[i] = 1e10f;
    }

    // idx[0] = 0: everyone fetches point 0 (same-address broadcast load).
    float lx = __ldg(xs), ly = __ldg(ys), lz = __ldg(zs);
    if (rank == 0 && tid == 0) {
        ob[0]          = lx;
        ob[NPOINT]     = ly;
        ob[2 * NPOINT] = lz;
    }

    for (int j = 1; j < NPOINT; ++j) {
        // ---- update temps, thread-local argmax (first occurrence on ties) ----
        float bv = -1.0f;
        int   bs = 0;
#pragma unroll
        for (int i = 0; i < P; ++i) {
            const float dx = __fsub_rn(xr[i], lx);
            const float dy = __fsub_rn(yr[i], ly);
            const float dz = __fsub_rn(zr[i], lz);
            const float d2 = __fadd_rn(
                __fadd_rn(__fmul_rn(dx, dx), __fmul_rn(dy, dy)),
                __fmul_rn(dz, dz));
            float t = fminf(tmp[i], d2);
            tmp[i] = t;
            if (t > bv) { bv = t; bs = i; }   // ascending i => lowest idx kept
        }
        const uint32_t idx = (uint32_t)(pbase + bs * T + tid);
        unsigned long long key =
            ((unsigned long long)__float_as_uint(bv) << 32) | (uint32_t)(~idx);

        // ---- warp argmax (max of monotone keys) ----
#pragma unroll
        for (int off = 16; off; off >>= 1) {
            const unsigned long long o = __shfl_down_sync(0xffffffffu, key, off);
            if (o > key) key = o;
        }
        if (l == 0) s_wkey[w] = key;
        __syncthreads();

        const int p = j & 1;
        if (w == 0) {
            unsigned long long k = (l < NW) ? s_wkey[l] : 0ull;
#pragma unroll
            for (int off = 16; off; off >>= 1) {
                const unsigned long long o = __shfl_down_sync(0xffffffffu, k, off);
                if (o > k) k = o;
            }
            if (l == 0) {
                const uint32_t widx = ~(uint32_t)k;      // CTA-best global idx
                const float cx = __ldg(xs + widx);       // L1-resident (48KB/plane slice)
                const float cy = __ldg(ys + widx);
                const float cz = __ldg(zs + widx);
                const unsigned long long xy =
                    ((unsigned long long)__float_as_uint(cy) << 32) |
                    (unsigned long long)__float_as_uint(cx);
                const uint32_t zb = __float_as_uint(cz);
                const uint32_t local = smem_u32(&s_slot[p][rank]);
#pragma unroll
                for (int dst = 0; dst < CLUSTER; ++dst) {
                    uint32_t rem;
                    asm volatile("mapa.shared::cluster.u32 %0, %1, %2;"
                                 : "=r"(rem) : "r"(local), "r"(dst));
                    asm volatile("st.shared::cluster.b64 [%0], %1;"
                                 :: "r"(rem), "l"(k) : "memory");
                    asm volatile("st.shared::cluster.b64 [%0+8], %1;"
                                 :: "r"(rem), "l"(xy) : "memory");
                    asm volatile("st.shared::cluster.b32 [%0+16], %1;"
                                 :: "r"(rem), "r"(zb) : "memory");
                }
            }
        }

        // arrive has release semantics (orders the shared::cluster stores);
        // wait has acquire semantics.
        asm volatile("barrier.cluster.arrive.aligned;" ::: "memory");
        asm volatile("barrier.cluster.wait.aligned;" ::: "memory");

        // ---- every thread picks the cluster winner from its own smem ----
        unsigned long long wk = s_slot[p][0].key;
        int wc = 0;
#pragma unroll
        for (int c = 1; c < CLUSTER; ++c) {
            const unsigned long long kk = s_slot[p][c].key;
            if (kk > wk) { wk = kk; wc = c; }
        }
        lx = s_slot[p][wc].x;
        ly = s_slot[p][wc].y;
        lz = s_slot[p][wc].z;

        if (rank == 0 && tid == 0) {
            ob[j]              = lx;
            ob[NPOINT + j]     = ly;
            ob[2 * NPOINT + j] = lz;
        }
    }
}

extern "C" void kernel_launch(void* const* d_in, const int* in_sizes, int n_in,
                              void* d_out, int out_size)
{
    (void)in_sizes; (void)n_in; (void)out_size;
    const float* xyz_t = (const float*)d_in[1];   // points_xyz_t: (B, 3, N)
    float* out = (float*)d_out;                   // (B, 3, NPOINT)
    fps_cluster_kernel<<<BATCH * CLUSTER, T>>>(xyz_t, out);
}